// round 16
// baseline (speedup 1.0000x reference)
#include <cuda_runtime.h>
#include <cuda_fp16.h>

#define AA 16      // agents
#define EE 128     // embed dim
#define EPH 136    // f16 elems per smem row (272B, staggered for ldmatrix)
#define EPB 272    // row bytes
#define NB 2       // batches per CTA
#define NEGV (-1e9f)

// Packed f16 weights: [m 8][nt 16][kk2 4][lane 32] uint4.
// m4 (W1) is pre-scaled by ln1_g[k]; m6 (Wqs) by ln2_g[k]/sqrt(E); m0 (Wq) by 0.25.
__device__ uint4 g_wpack[8 * 16 * 4 * 32];
// LN-fold vectors: c1,d1 (for W1), c2,d2 (for Wqs)
__device__ float g_c1[EE], g_d1[EE], g_c2[EE], g_d2[EE];

__device__ __forceinline__ unsigned pk2h(float lo, float hi) {
    unsigned r;
    asm("cvt.rn.f16x2.f32 %0, %1, %2;" : "=r"(r) : "f"(hi), "f"(lo));
    return r;
}
__device__ __forceinline__ float2 up2h(unsigned u) {
    const __half2 h = *reinterpret_cast<const __half2*>(&u);
    return __half22float2(h);
}
__device__ __forceinline__ unsigned hadd2u(unsigned a, unsigned b) {
    unsigned r;
    asm("add.f16x2 %0, %1, %2;" : "=r"(r) : "r"(a), "r"(b));
    return r;
}
__device__ __forceinline__ float tanh_fast(float x) {
    float r;
    asm("tanh.approx.f32 %0, %1;" : "=f"(r) : "f"(x));
    return r;
}
__device__ __forceinline__ unsigned scvt(const void* p) {
    return (unsigned)__cvta_generic_to_shared(p);
}
__device__ __forceinline__ void ldsm4(unsigned& r0, unsigned& r1, unsigned& r2, unsigned& r3,
                                      unsigned a) {
    asm volatile("ldmatrix.sync.aligned.m8n8.x4.shared.b16 {%0,%1,%2,%3}, [%4];"
                 : "=r"(r0), "=r"(r1), "=r"(r2), "=r"(r3) : "r"(a));
}
__device__ __forceinline__ void ldsm4t(unsigned& r0, unsigned& r1, unsigned& r2, unsigned& r3,
                                       unsigned a) {
    asm volatile("ldmatrix.sync.aligned.m8n8.x4.trans.shared.b16 {%0,%1,%2,%3}, [%4];"
                 : "=r"(r0), "=r"(r1), "=r"(r2), "=r"(r3) : "r"(a));
}
__device__ __forceinline__ void mmah(unsigned d[2], unsigned a0, unsigned a1, unsigned a2,
                                     unsigned a3, unsigned b0, unsigned b1) {
    asm("mma.sync.aligned.m16n8k16.row.col.f16.f16.f16.f16 "
        "{%0,%1}, {%2,%3,%4,%5}, {%6,%7}, {%0,%1};"
        : "+r"(d[0]), "+r"(d[1])
        : "r"(a0), "r"(a1), "r"(a2), "r"(a3), "r"(b0), "r"(b1));
}
__device__ __forceinline__ void mmaf(float d[4], unsigned a0, unsigned a1, unsigned a2,
                                     unsigned a3, unsigned b0, unsigned b1) {
    asm("mma.sync.aligned.m16n8k16.row.col.f32.f16.f16.f32 "
        "{%0,%1,%2,%3}, {%4,%5,%6,%7}, {%8,%9}, {%0,%1,%2,%3};"
        : "+f"(d[0]), "+f"(d[1]), "+f"(d[2]), "+f"(d[3])
        : "r"(a0), "r"(a1), "r"(a2), "r"(a3), "r"(b0), "r"(b1));
}

// ---- prepass 1: repack weights into f16 fragment order (with LN-g folds) ----
__global__ void __launch_bounds__(128) pack_weights_kernel(
    const float* __restrict__ Wq, const float* __restrict__ Wk,
    const float* __restrict__ Wv, const float* __restrict__ Wo,
    const float* __restrict__ W1, const float* __restrict__ W2,
    const float* __restrict__ Wqs, const float* __restrict__ Wks,
    const float* __restrict__ ln1_g, const float* __restrict__ ln2_g)
{
    const int idx = blockIdx.x * blockDim.x + threadIdx.x;   // 0..16383
    const int l  = idx & 31;
    const int k2 = (idx >> 5) & 3;
    const int nt = (idx >> 7) & 15;
    const int m  = idx >> 11;
    const float* W; float sc = 1.f;
    switch (m) {
        case 0: W = Wq; sc = 0.25f; break;                    // fold 1/sqrt(dh)
        case 1: W = Wk; break;
        case 2: W = Wv; break;
        case 3: W = Wo; break;
        case 4: W = W1; break;                                // *ln1_g[k] per-k below
        case 5: W = W2; break;
        case 6: W = Wqs; sc = 0.08838834764831845f; break;    // *ln2_g[k]/sqrt(E)
        default: W = Wks; break;
    }
    const int n  = nt * 8 + (l >> 2);
    const int kb = k2 * 32 + 2 * (l & 3);
    float v[8]; const int ko[8] = {0, 1, 8, 9, 16, 17, 24, 25};
#pragma unroll
    for (int i = 0; i < 8; i++) {
        const int k = kb + ko[i];
        float s = sc;
        if (m == 4) s = __ldg(&ln1_g[k]);
        else if (m == 6) s = sc * __ldg(&ln2_g[k]);
        v[i] = W[k * EE + n] * s;
    }
    uint4 o;
    o.x = pk2h(v[0], v[1]); o.y = pk2h(v[2], v[3]);
    o.z = pk2h(v[4], v[5]); o.w = pk2h(v[6], v[7]);
    g_wpack[idx] = o;
}

// ---- prepass 2: LN-fold column vectors c/d ----
__global__ void __launch_bounds__(128) cvec_kernel(
    const float* __restrict__ W1, const float* __restrict__ b1v,
    const float* __restrict__ ln1_g, const float* __restrict__ ln1_b,
    const float* __restrict__ Wqs,
    const float* __restrict__ ln2_g, const float* __restrict__ ln2_b)
{
    const int n = threadIdx.x;
    if (blockIdx.x == 0) {
        float c = 0.f, d = 0.f;
#pragma unroll 4
        for (int k = 0; k < EE; k++) {
            const float wv = __ldg(&W1[k * EE + n]);
            c = fmaf(__ldg(&ln1_g[k]), wv, c);
            d = fmaf(__ldg(&ln1_b[k]), wv, d);
        }
        g_c1[n] = c;
        g_d1[n] = d + __ldg(&b1v[n]);
    } else {
        const float s = 0.08838834764831845f;
        float c = 0.f, d = 0.f;
#pragma unroll 4
        for (int k = 0; k < EE; k++) {
            const float wv = __ldg(&Wqs[k * EE + n]);
            c = fmaf(__ldg(&ln2_g[k]), wv, c);
            d = fmaf(__ldg(&ln2_b[k]), wv, d);
        }
        g_c2[n] = c * s;
        g_d2[n] = d * s;
    }
}

enum { MRAW = 0, MRES_ST = 1, MLN_RELU = 2, MLN2_RES_ST = 3 };

// Final per-row LN stats from 4 warp-partials.
__device__ __forceinline__ void ln_stats(const float2 (*st)[16][4], int nb, int r,
                                         float& mu, float& iv) {
    const float4* sp = (const float4*)&st[nb][r][0];
    const float4 a = sp[0], b = sp[1];
    const float S = a.x + a.z + b.x + b.z;
    const float Q = a.y + a.w + b.y + b.w;
    mu = S * (1.f / 128.f);
    const float var = Q * (1.f / 128.f) - mu * mu;
    iv = rsqrtf(var + 1e-5f);
}

// acc = X @ W for this warp's 32 cols (packed f16x2 pairs).
template<bool PRE>
__device__ __forceinline__ void mm_acc(
    const __half (*Xs)[AA][EPH], const uint4* __restrict__ Wp,
    int w, int l, unsigned offA, unsigned acc[NB][4][2], const uint4* pre)
{
#pragma unroll
    for (int nb = 0; nb < NB; nb++)
#pragma unroll
        for (int nt = 0; nt < 4; nt++) { acc[nb][nt][0] = 0u; acc[nb][nt][1] = 0u; }
    const unsigned xb0 = scvt(&Xs[0][0][0]) + offA;
    const unsigned xb1 = scvt(&Xs[1][0][0]) + offA;
#pragma unroll
    for (int k2 = 0; k2 < 4; k2++) {
        uint4 wfr[4];
        if (PRE && k2 == 0) {
#pragma unroll
            for (int nt = 0; nt < 4; nt++) wfr[nt] = pre[nt];
        } else {
#pragma unroll
            for (int nt = 0; nt < 4; nt++)
                wfr[nt] = __ldg(&Wp[(((w * 4 + nt) * 4) + k2) * 32 + l]);
        }
#pragma unroll
        for (int nb = 0; nb < NB; nb++) {
            const unsigned xb = nb ? xb1 : xb0;
            unsigned a0, a1, a2, a3, c0, c1, c2, c3;
            ldsm4(a0, a1, a2, a3, xb + (2 * k2) * 32);
            ldsm4(c0, c1, c2, c3, xb + (2 * k2 + 1) * 32);
#pragma unroll
            for (int nt = 0; nt < 4; nt++) {
                mmah(acc[nb][nt], a0, a1, a2, a3, wfr[nt].x, wfr[nt].y);
                mmah(acc[nb][nt], c0, c1, c2, c3, wfr[nt].z, wfr[nt].w);
            }
        }
    }
}

// GEMM phase with LN-folded epilogues.
template<int MODE, bool PRE>
__device__ __forceinline__ void mm_phase(
    const __half (*Xs)[AA][EPH], __half (*Ys)[AA][EPH],
    const __half (*Rs)[AA][EPH],
    const float* __restrict__ cv, const float* __restrict__ dv,
    const float* __restrict__ bias2, const float* __restrict__ g1v,
    const float* __restrict__ bl1v,
    const float2 (*stIn)[16][4], float2 (*stOut)[16][4],
    const uint4* __restrict__ Wp, int w, int l, unsigned offA, int r0, int cq,
    const uint4* pre = nullptr)
{
    unsigned acc[NB][4][2];
    mm_acc<PRE>(Xs, Wp, w, l, offA, acc, pre);
#pragma unroll
    for (int nb = 0; nb < NB; nb++) {
        char* yb = (char*)&Ys[nb][0][0];
        const char* rb = (MODE == MRES_ST || MODE == MLN2_RES_ST)
                       ? (const char*)&Rs[nb][0][0] : nullptr;
        float mu0 = 0.f, iv0 = 0.f, mu8 = 0.f, iv8 = 0.f;
        if (MODE == MLN_RELU || MODE == MLN2_RES_ST) {
            ln_stats(stIn, nb, r0, mu0, iv0);
            ln_stats(stIn, nb, r0 + 8, mu8, iv8);
        }
        float s0 = 0.f, q0 = 0.f, s8 = 0.f, q8 = 0.f;   // stats accumulators
#pragma unroll
        for (int nt = 0; nt < 4; nt++) {
            const int colb = (w * 4 + nt) * 8 + cq;
            const unsigned off0 = r0 * EPB + colb * 2;
            const unsigned off1 = off0 + 8 * EPB;
            if (MODE == MRAW) {
                *(unsigned*)(yb + off0) = acc[nb][nt][0];
                *(unsigned*)(yb + off1) = acc[nb][nt][1];
            } else if (MODE == MRES_ST) {
                const unsigned y0 = hadd2u(acc[nb][nt][0], *(const unsigned*)(rb + off0));
                const unsigned y1 = hadd2u(acc[nb][nt][1], *(const unsigned*)(rb + off1));
                *(unsigned*)(yb + off0) = y0;
                *(unsigned*)(yb + off1) = y1;
                const float2 f0 = up2h(y0), f1 = up2h(y1);
                s0 += f0.x + f0.y; q0 = fmaf(f0.x, f0.x, fmaf(f0.y, f0.y, q0));
                s8 += f1.x + f1.y; q8 = fmaf(f1.x, f1.x, fmaf(f1.y, f1.y, q8));
            } else if (MODE == MLN_RELU) {
                const float2 c  = __ldg((const float2*)&cv[colb]);
                const float2 dd = __ldg((const float2*)&dv[colb]);
                const float2 f0 = up2h(acc[nb][nt][0]);
                const float2 f1 = up2h(acc[nb][nt][1]);
                const float bn0 = -iv0 * mu0, bn8 = -iv8 * mu8;
                const float v0x = fmaxf(fmaf(iv0, f0.x, fmaf(bn0, c.x, dd.x)), 0.f);
                const float v0y = fmaxf(fmaf(iv0, f0.y, fmaf(bn0, c.y, dd.y)), 0.f);
                const float v1x = fmaxf(fmaf(iv8, f1.x, fmaf(bn8, c.x, dd.x)), 0.f);
                const float v1y = fmaxf(fmaf(iv8, f1.y, fmaf(bn8, c.y, dd.y)), 0.f);
                *(unsigned*)(yb + off0) = pk2h(v0x, v0y);
                *(unsigned*)(yb + off1) = pk2h(v1x, v1y);
            } else {  // MLN2_RES_ST: z = acc + b2 + LN1(y); stats of z
                const float2 b2 = __ldg((const float2*)&bias2[colb]);
                const float2 gg = __ldg((const float2*)&g1v[colb]);
                const float2 bb = __ldg((const float2*)&bl1v[colb]);
                const float2 y0 = up2h(*(const unsigned*)(rb + off0));
                const float2 y1 = up2h(*(const unsigned*)(rb + off1));
                const float2 f0 = up2h(acc[nb][nt][0]);
                const float2 f1 = up2h(acc[nb][nt][1]);
                const float z0x = f0.x + b2.x + fmaf((y0.x - mu0) * iv0, gg.x, bb.x);
                const float z0y = f0.y + b2.y + fmaf((y0.y - mu0) * iv0, gg.y, bb.y);
                const float z1x = f1.x + b2.x + fmaf((y1.x - mu8) * iv8, gg.x, bb.x);
                const float z1y = f1.y + b2.y + fmaf((y1.y - mu8) * iv8, gg.y, bb.y);
                *(unsigned*)(yb + off0) = pk2h(z0x, z0y);
                *(unsigned*)(yb + off1) = pk2h(z1x, z1y);
                s0 += z0x + z0y; q0 = fmaf(z0x, z0x, fmaf(z0y, z0y, q0));
                s8 += z1x + z1y; q8 = fmaf(z1x, z1x, fmaf(z1y, z1y, q8));
            }
        }
        if (MODE == MRES_ST || MODE == MLN2_RES_ST) {
            s0 += __shfl_xor_sync(0xffffffffu, s0, 1); s0 += __shfl_xor_sync(0xffffffffu, s0, 2);
            q0 += __shfl_xor_sync(0xffffffffu, q0, 1); q0 += __shfl_xor_sync(0xffffffffu, q0, 2);
            s8 += __shfl_xor_sync(0xffffffffu, s8, 1); s8 += __shfl_xor_sync(0xffffffffu, s8, 2);
            q8 += __shfl_xor_sync(0xffffffffu, q8, 1); q8 += __shfl_xor_sync(0xffffffffu, q8, 2);
            if ((l & 3) == 0) {
                stOut[nb][r0][w]     = make_float2(s0, q0);
                stOut[nb][r0 + 8][w] = make_float2(s8, q8);
            }
        }
    }
}

__device__ __forceinline__ void wpre_load(uint4 pre[4], const uint4* __restrict__ Wp,
                                          int w, int l) {
#pragma unroll
    for (int nt = 0; nt < 4; nt++)
        pre[nt] = __ldg(&Wp[((w * 4 + nt) * 4) * 32 + l]);
}

__global__ void __launch_bounds__(128, 6)
conflict_model_kernel(
    const float* __restrict__ agent_embed,  // [B,16,128]
    const float* __restrict__ city_embed,   // [B,128,128]
    const int*   __restrict__ acts,         // [B,16]
    const float* __restrict__ ln1_g, const float* __restrict__ ln1_b,
    const float* __restrict__ b2v,
    float* __restrict__ out)                // [B,16,16]
{
    __shared__ __align__(16) __half sA[NB][AA][EPH];   // agent (ks source)
    __shared__ __align__(16) __half sX[NB][AA][EPH];   // selected -> z (raw, pre-LN2)
    __shared__ __align__(16) __half sV[NB][AA][EPH];   // v -> y (raw, pre-LN1) -> scratch
    __shared__ __align__(16) __half sW[NB][AA][EPH];   // attnO -> hidden -> scratch
    __shared__ float2 sSt1[NB][16][4];                 // LN1 partial stats
    __shared__ float2 sSt2[NB][16][4];                 // LN2 partial stats
    __shared__ unsigned s_mask[NB][AA];

    const int t = threadIdx.x;
    const int w = t >> 5, l = t & 31;
    const int hv = w & 1, nbw = w >> 1;
    const int r0 = l >> 2, cq = 2 * (l & 3);
    const int b0 = blockIdx.x * NB;

    const unsigned offA = (unsigned)(((l & 7) + ((l >> 3) & 1) * 8) * EPB + ((l >> 4) & 1) * 16);

    uint4 pre[4];

    // ---- masks in registers (every warp); warp 0 publishes for final phase ----
    const int av = __ldg(&acts[(b0 + (l >> 4)) * AA + (l & 15)]);
    unsigned msk = 0;
#pragma unroll
    for (int j = 0; j < AA; j++) {
        const int aj = __shfl_sync(0xffffffffu, av, (l & 16) + j);
        const bool conflict = (av == 0) ? (j == (l & 15)) : (aj == av);
        if (!conflict) msk |= (1u << j);
    }
    if (w == 0) s_mask[l >> 4][l & 15] = msk;
    const unsigned mA0 = __shfl_sync(0xffffffffu, msk, r0);
    const unsigned mA1 = __shfl_sync(0xffffffffu, msk, r0 + 8);
    const unsigned mB0 = __shfl_sync(0xffffffffu, msk, 16 + r0);
    const unsigned mB1 = __shfl_sync(0xffffffffu, msk, 16 + r0 + 8);

    // ---- load agent + gathered city rows (acts via shuffle, no smem dep) ----
#pragma unroll
    for (int rr = 0; rr < 8; rr++) {
        const int r = hv * 8 + rr;
        const float4 v = *reinterpret_cast<const float4*>(
            agent_embed + ((size_t)(b0 + nbw) * AA + r) * EE + 4 * l);
        uint2 p; p.x = pk2h(v.x, v.y); p.y = pk2h(v.z, v.w);
        *(uint2*)((char*)&sA[nbw][r][0] + 8 * l) = p;
        const int ci = __shfl_sync(0xffffffffu, av, nbw * 16 + r);
        const float4 u = *reinterpret_cast<const float4*>(
            city_embed + ((size_t)(b0 + nbw) * 128 + ci) * EE + 4 * l);
        uint2 q; q.x = pk2h(u.x, u.y); q.y = pk2h(u.z, u.w);
        *(uint2*)((char*)&sX[nbw][r][0] + 8 * l) = q;
    }
    wpre_load(pre, g_wpack + 2 * 2048, w, l);   // prefetch Wv k2=0
    __syncthreads();

    // ---- v -> smem ; k, q -> packed register fragments ----
    mm_phase<MRAW, true>(sA, sV, nullptr, nullptr, nullptr, nullptr, nullptr, nullptr,
                         nullptr, nullptr, g_wpack + 2 * 2048, w, l, offA, r0, cq, pre);
    unsigned kp[NB][4][2], qp[NB][4][2];
    mm_acc<false>(sA, g_wpack + 1 * 2048, w, l, offA, kp, nullptr);
    mm_acc<false>(sX, g_wpack + 0 * 2048, w, l, offA, qp, nullptr);  // Wq pre-scaled
    __syncwarp();  // V tile (cols 32w) is warp-private

    // ---- attention: warp w handles heads 2w, 2w+1 for BOTH batches ----
#pragma unroll
    for (int nb = 0; nb < NB; nb++) {
        const unsigned vb = scvt(&sV[nb][0][0]);
        const unsigned m0 = nb ? mB0 : mA0;
        const unsigned m1 = nb ? mB1 : mA1;
#pragma unroll
        for (int hh = 0; hh < 2; hh++) {
            const int h = 2 * w + hh;
            const unsigned cb = 32u * h;
            const unsigned a0 = qp[nb][2 * hh][0], a1 = qp[nb][2 * hh][1];
            const unsigned a2 = qp[nb][2 * hh + 1][0], a3 = qp[nb][2 * hh + 1][1];
            float s0[4] = {0, 0, 0, 0}, s1[4] = {0, 0, 0, 0};
            mmaf(s0, a0, a1, a2, a3, kp[nb][2 * hh][0], kp[nb][2 * hh + 1][0]);
            mmaf(s1, a0, a1, a2, a3, kp[nb][2 * hh][1], kp[nb][2 * hh + 1][1]);
            if ((m0 >> cq) & 1)       s0[0] = NEGV;
            if ((m0 >> (cq + 1)) & 1) s0[1] = NEGV;
            if ((m1 >> cq) & 1)       s0[2] = NEGV;
            if ((m1 >> (cq + 1)) & 1) s0[3] = NEGV;
            if ((m0 >> (cq + 8)) & 1) s1[0] = NEGV;
            if ((m0 >> (cq + 9)) & 1) s1[1] = NEGV;
            if ((m1 >> (cq + 8)) & 1) s1[2] = NEGV;
            if ((m1 >> (cq + 9)) & 1) s1[3] = NEGV;
            float mx0 = fmaxf(fmaxf(s0[0], s0[1]), fmaxf(s1[0], s1[1]));
            float mx1 = fmaxf(fmaxf(s0[2], s0[3]), fmaxf(s1[2], s1[3]));
            mx0 = fmaxf(mx0, __shfl_xor_sync(0xffffffffu, mx0, 1));
            mx0 = fmaxf(mx0, __shfl_xor_sync(0xffffffffu, mx0, 2));
            mx1 = fmaxf(mx1, __shfl_xor_sync(0xffffffffu, mx1, 1));
            mx1 = fmaxf(mx1, __shfl_xor_sync(0xffffffffu, mx1, 2));
            s0[0] = __expf(s0[0] - mx0); s0[1] = __expf(s0[1] - mx0);
            s1[0] = __expf(s1[0] - mx0); s1[1] = __expf(s1[1] - mx0);
            s0[2] = __expf(s0[2] - mx1); s0[3] = __expf(s0[3] - mx1);
            s1[2] = __expf(s1[2] - mx1); s1[3] = __expf(s1[3] - mx1);
            float sm0 = s0[0] + s0[1] + s1[0] + s1[1];
            float sm1 = s0[2] + s0[3] + s1[2] + s1[3];
            sm0 += __shfl_xor_sync(0xffffffffu, sm0, 1);
            sm0 += __shfl_xor_sync(0xffffffffu, sm0, 2);
            sm1 += __shfl_xor_sync(0xffffffffu, sm1, 1);
            sm1 += __shfl_xor_sync(0xffffffffu, sm1, 2);
            const float inv0 = 1.f / sm0, inv1 = 1.f / sm1;
            const unsigned p0 = pk2h(s0[0], s0[1]);
            const unsigned p1 = pk2h(s0[2], s0[3]);
            const unsigned p2 = pk2h(s1[0], s1[1]);
            const unsigned p3 = pk2h(s1[2], s1[3]);
            unsigned v0, v1, v2, v3;
            ldsm4t(v0, v1, v2, v3, vb + offA + cb);
            float o0[4] = {0, 0, 0, 0}, o1[4] = {0, 0, 0, 0};
            mmaf(o0, p0, p1, p2, p3, v0, v1);
            mmaf(o1, p0, p1, p2, p3, v2, v3);
            char* yb = (char*)&sW[nb][0][0];
            const unsigned c0 = r0 * EPB + (16 * h + cq) * 2;
            const unsigned c1 = c0 + 8 * EPB;
            *(unsigned*)(yb + c0)      = pk2h(o0[0] * inv0, o0[1] * inv0);
            *(unsigned*)(yb + c1)      = pk2h(o0[2] * inv1, o0[3] * inv1);
            *(unsigned*)(yb + c0 + 16) = pk2h(o1[0] * inv0, o1[1] * inv0);
            *(unsigned*)(yb + c1 + 16) = pk2h(o1[2] * inv1, o1[3] * inv1);
        }
    }
    wpre_load(pre, g_wpack + 3 * 2048, w, l);   // prefetch Wo k2=0
    __syncthreads();

    // ---- y = attnO @ Wo + selected -> sV (raw) + LN1 stats ----
    mm_phase<MRES_ST, true>(sW, sV, sX, nullptr, nullptr, nullptr, nullptr, nullptr,
                            nullptr, sSt1, g_wpack + 3 * 2048, w, l, offA, r0, cq, pre);
    wpre_load(pre, g_wpack + 4 * 2048, w, l);   // prefetch W1' k2=0
    __syncthreads();

    // ---- hidden = relu(LN1(y) @ W1 + b1) via fold -> sW ----
    mm_phase<MLN_RELU, true>(sV, sW, nullptr, g_c1, g_d1, nullptr, nullptr, nullptr,
                             sSt1, nullptr, g_wpack + 4 * 2048, w, l, offA, r0, cq, pre);
    wpre_load(pre, g_wpack + 5 * 2048, w, l);   // prefetch W2 k2=0
    __syncthreads();

    // ---- z = hidden @ W2 + b2 + LN1(y) -> sX (raw) + LN2 stats ----
    mm_phase<MLN2_RES_ST, true>(sW, sX, sV, nullptr, nullptr, b2v, ln1_g, ln1_b,
                                sSt1, sSt2, g_wpack + 5 * 2048, w, l, offA, r0, cq, pre);
    wpre_load(pre, g_wpack + 6 * 2048, w, l);   // prefetch Wqs'' k2=0
    __syncthreads();

    // ---- qs = LN2(z) @ Wqs (folded), ks = agent @ Wks; per-warp partial logits ----
    {
        unsigned qs2[NB][4][2], ks2[NB][4][2];
        mm_acc<true>(sX, g_wpack + 6 * 2048, w, l, offA, qs2, pre);
        mm_acc<false>(sA, g_wpack + 7 * 2048, w, l, offA, ks2, nullptr);
        // LN2 fold adjust on qs fragments
#pragma unroll
        for (int nb = 0; nb < NB; nb++) {
            float mu0, iv0, mu8, iv8;
            ln_stats(sSt2, nb, r0, mu0, iv0);
            ln_stats(sSt2, nb, r0 + 8, mu8, iv8);
            const float bn0 = -iv0 * mu0, bn8 = -iv8 * mu8;
#pragma unroll
            for (int nt = 0; nt < 4; nt++) {
                const int colb = (w * 4 + nt) * 8 + cq;
                const float2 c = __ldg((const float2*)&g_c2[colb]);
                const float2 d = __ldg((const float2*)&g_d2[colb]);
                float2 f0 = up2h(qs2[nb][nt][0]);
                float2 f1 = up2h(qs2[nb][nt][1]);
                f0.x = fmaf(iv0, f0.x, fmaf(bn0, c.x, d.x));
                f0.y = fmaf(iv0, f0.y, fmaf(bn0, c.y, d.y));
                f1.x = fmaf(iv8, f1.x, fmaf(bn8, c.x, d.x));
                f1.y = fmaf(iv8, f1.y, fmaf(bn8, c.y, d.y));
                qs2[nb][nt][0] = pk2h(f0.x, f0.y);
                qs2[nb][nt][1] = pk2h(f1.x, f1.y);
            }
        }
        // partial logits over this warp's 32-wide E slice
#pragma unroll
        for (int nb = 0; nb < NB; nb++) {
            float d0[4] = {0, 0, 0, 0}, d1[4] = {0, 0, 0, 0};
#pragma unroll
            for (int j = 0; j < 2; j++) {
                const unsigned a0 = qs2[nb][2 * j][0], a1 = qs2[nb][2 * j][1];
                const unsigned a2 = qs2[nb][2 * j + 1][0], a3 = qs2[nb][2 * j + 1][1];
                mmaf(d0, a0, a1, a2, a3, ks2[nb][2 * j][0], ks2[nb][2 * j + 1][0]);
                mmaf(d1, a0, a1, a2, a3, ks2[nb][2 * j][1], ks2[nb][2 * j + 1][1]);
            }
            float* pw = (float*)(nb ? (void*)&sW[0][0][0] : (void*)&sV[0][0][0]) + w * 320;
            *(float2*)&pw[r0 * 20 + cq]            = make_float2(d0[0], d0[1]);
            *(float2*)&pw[(r0 + 8) * 20 + cq]      = make_float2(d0[2], d0[3]);
            *(float2*)&pw[r0 * 20 + 8 + cq]        = make_float2(d1[0], d1[1]);
            *(float2*)&pw[(r0 + 8) * 20 + 8 + cq]  = make_float2(d1[2], d1[3]);
        }
    }
    __syncthreads();

    // ---- reduce 4 warp-partials, tanh-clip, mask, store ----
    {
        const int nb = t >> 6;
        const int tt = t & 63;
        const int q  = tt >> 2;
        const int k0 = (tt & 3) * 4;
        const float* pb = (const float*)(nb ? (void*)&sW[0][0][0] : (void*)&sV[0][0][0]);
        const int o = q * 20 + k0;
        const float4 p0v = *(const float4*)&pb[o];
        const float4 p1v = *(const float4*)&pb[320 + o];
        const float4 p2v = *(const float4*)&pb[640 + o];
        const float4 p3v = *(const float4*)&pb[960 + o];
        const float sx = p0v.x + p1v.x + p2v.x + p3v.x;
        const float sy = p0v.y + p1v.y + p2v.y + p3v.y;
        const float sz = p0v.z + p1v.z + p2v.z + p3v.z;
        const float sw2 = p0v.w + p1v.w + p2v.w + p3v.w;
        const unsigned mq = s_mask[nb][q];
        float4 r;
        r.x = ((mq >> (k0 + 0)) & 1u) ? NEGV : 10.f * tanh_fast(sx);
        r.y = ((mq >> (k0 + 1)) & 1u) ? NEGV : 10.f * tanh_fast(sy);
        r.z = ((mq >> (k0 + 2)) & 1u) ? NEGV : 10.f * tanh_fast(sz);
        r.w = ((mq >> (k0 + 3)) & 1u) ? NEGV : 10.f * tanh_fast(sw2);
        *(float4*)&out[(size_t)(b0 + nb) * (AA * AA) + q * AA + k0] = r;
    }
}

extern "C" void kernel_launch(void* const* d_in, const int* in_sizes, int n_in,
                              void* d_out, int out_size) {
    const float* agent_embed = (const float*)d_in[0];
    const float* city_embed  = (const float*)d_in[1];
    const int*   acts        = (const int*)d_in[2];
    const float* Wq    = (const float*)d_in[3];
    const float* Wk    = (const float*)d_in[4];
    const float* Wv    = (const float*)d_in[5];
    const float* Wo    = (const float*)d_in[6];
    const float* ln1_g = (const float*)d_in[7];
    const float* ln1_b = (const float*)d_in[8];
    const float* W1    = (const float*)d_in[9];
    const float* b1v   = (const float*)d_in[10];
    const float* W2    = (const float*)d_in[11];
    const float* b2v   = (const float*)d_in[12];
    const float* ln2_g = (const float*)d_in[13];
    const float* ln2_b = (const float*)d_in[14];
    const float* Wqs   = (const float*)d_in[15];
    const float* Wks   = (const float*)d_in[16];

    const int B = in_sizes[0] / (AA * EE);

    pack_weights_kernel<<<128, 128>>>(Wq, Wk, Wv, Wo, W1, W2, Wqs, Wks, ln1_g, ln2_g);
    cvec_kernel<<<2, 128>>>(W1, b1v, ln1_g, ln1_b, Wqs, ln2_g, ln2_b);
    conflict_model_kernel<<<B / NB, 128>>>(
        agent_embed, city_embed, acts,
        ln1_g, ln1_b, b2v,
        (float*)d_out);
}